// round 10
// baseline (speedup 1.0000x reference)
#include <cuda_runtime.h>

// ---------------------------------------------------------------------------
// SpatialAttn2: B=16, L=32, N=256, P=16, H=4, F=12, HID=4, W=16
// out[B,W,F,N] | attn1[B,W,H,N,N] | attn2[B,W,N,N] | Wv1 | Wv2
// R10: R9 + Qd duplicated-pair smem (broadcast LDS.64, no per-k pk2 movs),
//      0.25*log2e folded into Q + raw ex2.approx, packed denominator adds.
// ---------------------------------------------------------------------------

#define N_   256
#define P_   16
#define H_   4
#define F_   12
#define HID_ 4
#define W_   16
#define L_   32
#define BW_  256

static const unsigned long long OFF_A1  = 786432ull;
static const unsigned long long OFF_A2  = 786432ull + 67108864ull;
static const unsigned long long OFF_WV1 = 786432ull + 67108864ull + 16777216ull;
static const unsigned long long OFF_WV2 = OFF_WV1 + 256ull;
static const long long TOT_FULL = 84672960ll;

#define QSCALE 0.36067376022224085f   // 0.25 * log2(e)

__device__ unsigned int g_maskbits[N_ * 8];

typedef unsigned long long u64;

__device__ __forceinline__ u64 pk2(float a, float b) {
    u64 r; asm("mov.b64 %0, {%1,%2};" : "=l"(r) : "f"(a), "f"(b)); return r;
}
__device__ __forceinline__ void upk2(u64 v, float& a, float& b) {
    asm("mov.b64 {%0,%1}, %2;" : "=f"(a), "=f"(b) : "l"(v));
}
__device__ __forceinline__ u64 fma2_(u64 a, u64 b, u64 c) {
    u64 d; asm("fma.rn.f32x2 %0, %1, %2, %3;" : "=l"(d) : "l"(a), "l"(b), "l"(c)); return d;
}
__device__ __forceinline__ u64 mul2_(u64 a, u64 b) {
    u64 d; asm("mul.rn.f32x2 %0, %1, %2;" : "=l"(d) : "l"(a), "l"(b)); return d;
}
__device__ __forceinline__ u64 add2_(u64 a, u64 b) {
    u64 d; asm("add.rn.f32x2 %0, %1, %2;" : "=l"(d) : "l"(a), "l"(b)); return d;
}
__device__ __forceinline__ float ex2_(float x) {
    float y; asm("ex2.approx.f32 %0, %1;" : "=f"(y) : "f"(x)); return y;
}
__device__ __forceinline__ u64 warp_sum2(u64 v) {
#pragma unroll
    for (int o = 16; o > 0; o >>= 1)
        v = add2_(v, __shfl_xor_sync(0xffffffffu, v, o));
    return v;
}

// ---------------------------------------------------------------------------
__global__ void pack_mask_kernel(const int* __restrict__ mask,
                                 const float* __restrict__ Wv1,
                                 const float* __restrict__ Wv2,
                                 float* __restrict__ out, int wW) {
    const int tid = threadIdx.x;
    const int row = blockIdx.x;
    int v = mask[row * N_ + tid];
    unsigned int bal = __ballot_sync(0xffffffffu, v > 0);
    if ((tid & 31) == 0) g_maskbits[row * 8 + (tid >> 5)] = bal;
    if (wW && row == 0) {
        out[OFF_WV1 + tid] = Wv1[tid];
        if (tid < 192) out[OFF_WV2 + tid] = Wv2[tid];
    }
}

// ---------------------------------------------------------------------------
struct __align__(16) Smem {
    float xT [P_][N_];
    float h1T[P_][N_];
    u64   Qd [N_][P_];           // duplicated (q,q) pairs, broadcast LDS.64
    float VT [F_][N_];
    unsigned char mbL[N_][32];   // per-(row,lane) mask byte
    float Wa1[H_][P_][P_];
    float Wv1[H_][P_][HID_];
    float Wa2[P_][P_];
    float Wv2[P_][F_];
};

__global__ void __launch_bounds__(256, 2)
spatial_attn_kernel(const float* __restrict__ inp,
                    const float* __restrict__ Wa1,
                    const float* __restrict__ Wv1,
                    const float* __restrict__ Wa2,
                    const float* __restrict__ Wv2,
                    float* __restrict__ out, int wA) {
    extern __shared__ char smraw[];
    Smem& S = *reinterpret_cast<Smem*>(smraw);
    const int tid  = threadIdx.x;
    const int lane = tid & 31;
    const int wid  = tid >> 5;
    const int bw   = blockIdx.x;
    const int b    = bw >> 4;
    const int w    = bw & 15;

    // ---- stage 0: load xT, weights; build mask byte table ------------------
#pragma unroll
    for (int p = 0; p < P_; p++)
        S.xT[p][tid] = inp[(b * L_ + w + p) * N_ + tid];
#pragma unroll
    for (int j = 0; j < 8; j++) {
        int idx = tid + 256 * j;
        int r = idx >> 3, g = idx & 7;
        unsigned A = g_maskbits[r * 8 + (g >> 1)];
        unsigned B = g_maskbits[r * 8 + 4 + (g >> 1)];
        int base = (g & 1) * 16;
        unsigned wd = 0;
#pragma unroll
        for (int i2 = 0; i2 < 4; i2++) {
            unsigned byte = ((A >> (base + 4 * i2)) & 0xFu)
                          | (((B >> (base + 4 * i2)) & 0xFu) << 4);
            wd |= byte << (8 * i2);
        }
        reinterpret_cast<unsigned*>(&S.mbL[0][0])[idx] = wd;
    }
#pragma unroll
    for (int k = 0; k < 4; k++)
        (&S.Wa1[0][0][0])[tid + 256 * k] = Wa1[tid + 256 * k];
    (&S.Wv1[0][0][0])[tid] = Wv1[tid];
    (&S.Wa2[0][0])[tid]    = Wa2[tid];
    if (tid < 192) (&S.Wv2[0][0])[tid] = Wv2[tid];
    __syncthreads();

    float* a1 = out + OFF_A1 + (unsigned long long)bw * (H_ * N_ * N_);
    float* a2 = out + OFF_A2 + (unsigned long long)bw * (N_ * N_);

    // =========================== layer 1 (4 heads) ===========================
#pragma unroll 1
    for (int h = 0; h < H_; h++) {
        // stage 1: Qd = (0.25*log2e) * X @ Wa1[h] dup-pairs; VT = (X@Wv1[h])^T
        {
            float q[P_], v[HID_];
#pragma unroll
            for (int j = 0; j < P_; j++) q[j] = 0.f;
#pragma unroll
            for (int o = 0; o < HID_; o++) v[o] = 0.f;
#pragma unroll
            for (int i = 0; i < P_; i++) {
                float xi = S.xT[i][tid];
#pragma unroll
                for (int j = 0; j < P_; j++) q[j] += xi * S.Wa1[h][i][j];
#pragma unroll
                for (int o = 0; o < HID_; o++) v[o] += xi * S.Wv1[h][i][o];
            }
#pragma unroll
            for (int j = 0; j < P_; j++) {
                float qs = q[j] * QSCALE;
                S.Qd[tid][j] = pk2(qs, qs);
            }
#pragma unroll
            for (int o = 0; o < HID_; o++) S.VT[o][tid] = v[o];
        }
        __syncthreads();

        float* a1h = a1 + h * N_ * N_;
#pragma unroll 1
        for (int rg = 0; rg < 8; rg++) {
            const int row0 = (wid << 5) + (rg << 2);
            // packed scores s2[c][r][pair]
            u64 s2[2][4][2];
#pragma unroll
            for (int c = 0; c < 2; c++)
#pragma unroll
                for (int r = 0; r < 4; r++) { s2[c][r][0] = 0ull; s2[c][r][1] = 0ull; }
#pragma unroll
            for (int k = 0; k < P_; k++) {
                u64 qq[4];
#pragma unroll
                for (int r = 0; r < 4; r++) qq[r] = S.Qd[row0 + r][k];
#pragma unroll
                for (int c = 0; c < 2; c++) {
                    ulonglong2 xv = *reinterpret_cast<const ulonglong2*>(
                        &S.xT[k][c * 128 + (lane << 2)]);
#pragma unroll
                    for (int r = 0; r < 4; r++) {
                        s2[c][r][0] = fma2_(qq[r], xv.x, s2[c][r][0]);
                        s2[c][r][1] = fma2_(qq[r], xv.y, s2[c][r][1]);
                    }
                }
            }
            // mask + exp2 in place; packed partial denominators
            float smr[4];
#pragma unroll
            for (int r = 0; r < 4; r++) {
                unsigned bb = S.mbL[row0 + r][lane];
                u64 dacc = 0ull;
#pragma unroll
                for (int c = 0; c < 2; c++)
#pragma unroll
                    for (int p = 0; p < 2; p++) {
                        float a_, b_; upk2(s2[c][r][p], a_, b_);
                        int kb = c * 4 + p * 2;
                        a_ = ((bb >> kb) & 1u)       ? ex2_(a_) : 0.f;
                        b_ = ((bb >> (kb + 1)) & 1u) ? ex2_(b_) : 0.f;
                        u64 e2 = pk2(a_, b_);
                        s2[c][r][p] = e2;
                        dacc = add2_(dacc, e2);
                    }
                float da, db; upk2(dacc, da, db);
                smr[r] = da + db;
            }
            // launch denominator chains (consumed AFTER aggregation)
            u64 d01 = warp_sum2(pk2(smr[0], smr[1]));
            u64 d23 = warp_sum2(pk2(smr[2], smr[3]));
            // aggregate RAW e (overlaps the SHFL chains)
            u64 acc2[4][HID_];
#pragma unroll
            for (int r = 0; r < 4; r++)
#pragma unroll
                for (int o = 0; o < HID_; o++) acc2[r][o] = 0ull;
#pragma unroll
            for (int c = 0; c < 2; c++) {
                const int m0 = c * 128 + (lane << 2);
#pragma unroll
                for (int o = 0; o < HID_; o++) {
                    ulonglong2 vv = *reinterpret_cast<const ulonglong2*>(&S.VT[o][m0]);
#pragma unroll
                    for (int r = 0; r < 4; r++) {
                        acc2[r][o] = fma2_(s2[c][r][0], vv.x, acc2[r][o]);
                        acc2[r][o] = fma2_(s2[c][r][1], vv.y, acc2[r][o]);
                    }
                }
            }
            // now consume denominators
            float inv[4];
            {
                float s0, s1, s2_, s3;
                upk2(d01, s0, s1); upk2(d23, s2_, s3);
                inv[0] = __frcp_rn(s0); inv[1] = __frcp_rn(s1);
                inv[2] = __frcp_rn(s2_); inv[3] = __frcp_rn(s3);
            }
            u64 inv2[4];
#pragma unroll
            for (int r = 0; r < 4; r++) inv2[r] = pk2(inv[r], inv[r]);
            // write normalized attn
            if (wA) {
#pragma unroll
                for (int c = 0; c < 2; c++) {
                    const int m0 = c * 128 + (lane << 2);
#pragma unroll
                    for (int r = 0; r < 4; r++) {
                        ulonglong2 st;
                        st.x = mul2_(s2[c][r][0], inv2[r]);
                        st.y = mul2_(s2[c][r][1], inv2[r]);
                        *reinterpret_cast<ulonglong2*>(&a1h[(row0 + r) * N_ + m0]) = st;
                    }
                }
            }
            // outputs: scale packed partial sums by inv, then reduce
#pragma unroll
            for (int r = 0; r < 4; r++) {
                float a0, b0, a1_, b1_, a2_, b2_, a3_, b3_;
                upk2(acc2[r][0], a0, b0);  upk2(acc2[r][1], a1_, b1_);
                upk2(acc2[r][2], a2_, b2_); upk2(acc2[r][3], a3_, b3_);
                u64 t01 = warp_sum2(mul2_(pk2(a0 + b0, a1_ + b1_), inv2[r]));
                u64 t23 = warp_sum2(mul2_(pk2(a2_ + b2_, a3_ + b3_), inv2[r]));
                if (lane == 0) {
                    float v0, v1, v2, v3;
                    upk2(t01, v0, v1); upk2(t23, v2, v3);
                    S.h1T[h * HID_ + 0][row0 + r] = v0;
                    S.h1T[h * HID_ + 1][row0 + r] = v1;
                    S.h1T[h * HID_ + 2][row0 + r] = v2;
                    S.h1T[h * HID_ + 3][row0 + r] = v3;
                }
            }
        }
        __syncthreads();
    }

    // ================================ layer 2 ================================
    {
        float q[P_], v[F_];
#pragma unroll
        for (int j = 0; j < P_; j++) q[j] = 0.f;
#pragma unroll
        for (int o = 0; o < F_; o++) v[o] = 0.f;
#pragma unroll
        for (int i = 0; i < P_; i++) {
            float xi = S.h1T[i][tid];
#pragma unroll
            for (int j = 0; j < P_; j++) q[j] += xi * S.Wa2[i][j];
#pragma unroll
            for (int o = 0; o < F_; o++) v[o] += xi * S.Wv2[i][o];
        }
#pragma unroll
        for (int j = 0; j < P_; j++) {
            float qs = q[j] * QSCALE;
            S.Qd[tid][j] = pk2(qs, qs);
        }
#pragma unroll
        for (int o = 0; o < F_; o++) S.VT[o][tid] = v[o];
    }
    __syncthreads();

    // layer2: 4-row blocking, F-split aggregation (2 groups of 6 outputs)
#pragma unroll 1
    for (int rg = 0; rg < 8; rg++) {
        const int row0 = (wid << 5) + (rg << 2);
        u64 s2[2][4][2];
#pragma unroll
        for (int c = 0; c < 2; c++)
#pragma unroll
            for (int r = 0; r < 4; r++) { s2[c][r][0] = 0ull; s2[c][r][1] = 0ull; }
#pragma unroll
        for (int k = 0; k < P_; k++) {
            u64 qq[4];
#pragma unroll
            for (int r = 0; r < 4; r++) qq[r] = S.Qd[row0 + r][k];
#pragma unroll
            for (int c = 0; c < 2; c++) {
                ulonglong2 xv = *reinterpret_cast<const ulonglong2*>(
                    &S.h1T[k][c * 128 + (lane << 2)]);
#pragma unroll
                for (int r = 0; r < 4; r++) {
                    s2[c][r][0] = fma2_(qq[r], xv.x, s2[c][r][0]);
                    s2[c][r][1] = fma2_(qq[r], xv.y, s2[c][r][1]);
                }
            }
        }
        float smr[4];
#pragma unroll
        for (int r = 0; r < 4; r++) {
            unsigned bb = S.mbL[row0 + r][lane];
            u64 dacc = 0ull;
#pragma unroll
            for (int c = 0; c < 2; c++)
#pragma unroll
                for (int p = 0; p < 2; p++) {
                    float a_, b_; upk2(s2[c][r][p], a_, b_);
                    int kb = c * 4 + p * 2;
                    a_ = ((bb >> kb) & 1u)       ? ex2_(a_) : 0.f;
                    b_ = ((bb >> (kb + 1)) & 1u) ? ex2_(b_) : 0.f;
                    u64 e2 = pk2(a_, b_);
                    s2[c][r][p] = e2;
                    dacc = add2_(dacc, e2);
                }
            float da, db; upk2(dacc, da, db);
            smr[r] = da + db;
        }
        u64 d01 = warp_sum2(pk2(smr[0], smr[1]));
        u64 d23 = warp_sum2(pk2(smr[2], smr[3]));

        // ---- group 0: outputs 0..5, raw-e aggregation (overlaps chains) ----
        u64 acc2[4][6];
#pragma unroll
        for (int r = 0; r < 4; r++)
#pragma unroll
            for (int o = 0; o < 6; o++) acc2[r][o] = 0ull;
#pragma unroll
        for (int c = 0; c < 2; c++) {
            const int m0 = c * 128 + (lane << 2);
#pragma unroll
            for (int o = 0; o < 6; o++) {
                ulonglong2 vv = *reinterpret_cast<const ulonglong2*>(&S.VT[o][m0]);
#pragma unroll
                for (int r = 0; r < 4; r++) {
                    acc2[r][o] = fma2_(s2[c][r][0], vv.x, acc2[r][o]);
                    acc2[r][o] = fma2_(s2[c][r][1], vv.y, acc2[r][o]);
                }
            }
        }
        float inv[4];
        {
            float s0, s1, s2_, s3;
            upk2(d01, s0, s1); upk2(d23, s2_, s3);
            inv[0] = __frcp_rn(s0); inv[1] = __frcp_rn(s1);
            inv[2] = __frcp_rn(s2_); inv[3] = __frcp_rn(s3);
        }
        u64 inv2[4];
#pragma unroll
        for (int r = 0; r < 4; r++) inv2[r] = pk2(inv[r], inv[r]);
#pragma unroll
        for (int r = 0; r < 4; r++) {
#pragma unroll
            for (int p = 0; p < 3; p++) {
                float a0, b0, a1_, b1_;
                upk2(acc2[r][2 * p], a0, b0);
                upk2(acc2[r][2 * p + 1], a1_, b1_);
                u64 t = warp_sum2(mul2_(pk2(a0 + b0, a1_ + b1_), inv2[r]));
                if (lane == 0) {
                    float v0, v1; upk2(t, v0, v1);
                    out[((unsigned long long)bw * F_ + 2 * p) * N_ + row0 + r]     = v0;
                    out[((unsigned long long)bw * F_ + 2 * p + 1) * N_ + row0 + r] = v1;
                }
            }
        }
        // write normalized attn2
        if (wA) {
#pragma unroll
            for (int c = 0; c < 2; c++) {
                const int m0 = c * 128 + (lane << 2);
#pragma unroll
                for (int r = 0; r < 4; r++) {
                    ulonglong2 st;
                    st.x = mul2_(s2[c][r][0], inv2[r]);
                    st.y = mul2_(s2[c][r][1], inv2[r]);
                    *reinterpret_cast<ulonglong2*>(&a2[(row0 + r) * N_ + m0]) = st;
                }
            }
        }
        // ---- group 1: outputs 6..11 ----
#pragma unroll
        for (int r = 0; r < 4; r++)
#pragma unroll
            for (int o = 0; o < 6; o++) acc2[r][o] = 0ull;
#pragma unroll
        for (int c = 0; c < 2; c++) {
            const int m0 = c * 128 + (lane << 2);
#pragma unroll
            for (int o = 0; o < 6; o++) {
                ulonglong2 vv = *reinterpret_cast<const ulonglong2*>(&S.VT[6 + o][m0]);
#pragma unroll
                for (int r = 0; r < 4; r++) {
                    acc2[r][o] = fma2_(s2[c][r][0], vv.x, acc2[r][o]);
                    acc2[r][o] = fma2_(s2[c][r][1], vv.y, acc2[r][o]);
                }
            }
        }
#pragma unroll
        for (int r = 0; r < 4; r++) {
#pragma unroll
            for (int p = 0; p < 3; p++) {
                float a0, b0, a1_, b1_;
                upk2(acc2[r][2 * p], a0, b0);
                upk2(acc2[r][2 * p + 1], a1_, b1_);
                u64 t = warp_sum2(mul2_(pk2(a0 + b0, a1_ + b1_), inv2[r]));
                if (lane == 0) {
                    float v0, v1; upk2(t, v0, v1);
                    out[((unsigned long long)bw * F_ + 6 + 2 * p) * N_ + row0 + r]     = v0;
                    out[((unsigned long long)bw * F_ + 6 + 2 * p + 1) * N_ + row0 + r] = v1;
                }
            }
        }
    }
}

// ---------------------------------------------------------------------------
extern "C" void kernel_launch(void* const* d_in, const int* in_sizes, int n_in,
                              void* d_out, int out_size) {
    const float* inp  = (const float*)d_in[0];
    const int*   mask = (const int*)  d_in[1];
    const float* Wa1  = (const float*)d_in[2];
    const float* Wv1  = (const float*)d_in[3];
    const float* Wa2  = (const float*)d_in[4];
    const float* Wv2  = (const float*)d_in[5];
    float* out = (float*)d_out;

    const int wA = (out_size >= (int)(OFF_A2 + (unsigned long long)BW_ * N_ * N_)) ? 1 : 0;
    const int wW = (out_size >= (int)TOT_FULL) ? 1 : 0;

    cudaFuncSetAttribute(spatial_attn_kernel,
                         cudaFuncAttributeMaxDynamicSharedMemorySize,
                         (int)sizeof(Smem));

    pack_mask_kernel<<<N_, 256>>>(mask, Wv1, Wv2, out, wW);
    spatial_attn_kernel<<<BW_, 256, sizeof(Smem)>>>(inp, Wa1, Wv1, Wa2, Wv2, out, wA);
}

// round 11
// speedup vs baseline: 1.1028x; 1.1028x over previous
#include <cuda_runtime.h>

// ---------------------------------------------------------------------------
// SpatialAttn2: B=16, L=32, N=256, P=16, H=4, F=12, HID=4, W=16
// out[B,W,F,N] | attn1[B,W,H,N,N] | attn2[B,W,N,N] | Wv1 | Wv2
// R11: R9 skeleton (Qs float4 staging) + QSCALE/ex2 fold + packed
//      denominator adds. (R10's Qd LDS.64 swap reverted: wrong pipe.)
// ---------------------------------------------------------------------------

#define N_   256
#define P_   16
#define H_   4
#define F_   12
#define HID_ 4
#define W_   16
#define L_   32
#define BW_  256

static const unsigned long long OFF_A1  = 786432ull;
static const unsigned long long OFF_A2  = 786432ull + 67108864ull;
static const unsigned long long OFF_WV1 = 786432ull + 67108864ull + 16777216ull;
static const unsigned long long OFF_WV2 = OFF_WV1 + 256ull;
static const long long TOT_FULL = 84672960ll;

#define QSCALE 0.36067376022224085f   // 0.25 * log2(e)

__device__ unsigned int g_maskbits[N_ * 8];

typedef unsigned long long u64;

__device__ __forceinline__ u64 pk2(float a, float b) {
    u64 r; asm("mov.b64 %0, {%1,%2};" : "=l"(r) : "f"(a), "f"(b)); return r;
}
__device__ __forceinline__ void upk2(u64 v, float& a, float& b) {
    asm("mov.b64 {%0,%1}, %2;" : "=f"(a), "=f"(b) : "l"(v));
}
__device__ __forceinline__ u64 fma2_(u64 a, u64 b, u64 c) {
    u64 d; asm("fma.rn.f32x2 %0, %1, %2, %3;" : "=l"(d) : "l"(a), "l"(b), "l"(c)); return d;
}
__device__ __forceinline__ u64 mul2_(u64 a, u64 b) {
    u64 d; asm("mul.rn.f32x2 %0, %1, %2;" : "=l"(d) : "l"(a), "l"(b)); return d;
}
__device__ __forceinline__ u64 add2_(u64 a, u64 b) {
    u64 d; asm("add.rn.f32x2 %0, %1, %2;" : "=l"(d) : "l"(a), "l"(b)); return d;
}
__device__ __forceinline__ float ex2_(float x) {
    float y; asm("ex2.approx.f32 %0, %1;" : "=f"(y) : "f"(x)); return y;
}
__device__ __forceinline__ u64 warp_sum2(u64 v) {
#pragma unroll
    for (int o = 16; o > 0; o >>= 1)
        v = add2_(v, __shfl_xor_sync(0xffffffffu, v, o));
    return v;
}

// ---------------------------------------------------------------------------
__global__ void pack_mask_kernel(const int* __restrict__ mask,
                                 const float* __restrict__ Wv1,
                                 const float* __restrict__ Wv2,
                                 float* __restrict__ out, int wW) {
    const int tid = threadIdx.x;
    const int row = blockIdx.x;
    int v = mask[row * N_ + tid];
    unsigned int bal = __ballot_sync(0xffffffffu, v > 0);
    if ((tid & 31) == 0) g_maskbits[row * 8 + (tid >> 5)] = bal;
    if (wW && row == 0) {
        out[OFF_WV1 + tid] = Wv1[tid];
        if (tid < 192) out[OFF_WV2 + tid] = Wv2[tid];
    }
}

// ---------------------------------------------------------------------------
struct __align__(16) Smem {
    float xT [P_][N_];
    float h1T[P_][N_];
    float Qs [N_][20];
    float VT [F_][N_];
    unsigned char mbL[N_][32];   // per-(row,lane) mask byte
    float Wa1[H_][P_][P_];
    float Wv1[H_][P_][HID_];
    float Wa2[P_][P_];
    float Wv2[P_][F_];
};

__global__ void __launch_bounds__(256, 2)
spatial_attn_kernel(const float* __restrict__ inp,
                    const float* __restrict__ Wa1,
                    const float* __restrict__ Wv1,
                    const float* __restrict__ Wa2,
                    const float* __restrict__ Wv2,
                    float* __restrict__ out, int wA) {
    extern __shared__ char smraw[];
    Smem& S = *reinterpret_cast<Smem*>(smraw);
    const int tid  = threadIdx.x;
    const int lane = tid & 31;
    const int wid  = tid >> 5;
    const int bw   = blockIdx.x;
    const int b    = bw >> 4;
    const int w    = bw & 15;

    // ---- stage 0: load xT, weights; build mask byte table ------------------
#pragma unroll
    for (int p = 0; p < P_; p++)
        S.xT[p][tid] = inp[(b * L_ + w + p) * N_ + tid];
#pragma unroll
    for (int j = 0; j < 8; j++) {
        int idx = tid + 256 * j;
        int r = idx >> 3, g = idx & 7;
        unsigned A = g_maskbits[r * 8 + (g >> 1)];
        unsigned B = g_maskbits[r * 8 + 4 + (g >> 1)];
        int base = (g & 1) * 16;
        unsigned wd = 0;
#pragma unroll
        for (int i2 = 0; i2 < 4; i2++) {
            unsigned byte = ((A >> (base + 4 * i2)) & 0xFu)
                          | (((B >> (base + 4 * i2)) & 0xFu) << 4);
            wd |= byte << (8 * i2);
        }
        reinterpret_cast<unsigned*>(&S.mbL[0][0])[idx] = wd;
    }
#pragma unroll
    for (int k = 0; k < 4; k++)
        (&S.Wa1[0][0][0])[tid + 256 * k] = Wa1[tid + 256 * k];
    (&S.Wv1[0][0][0])[tid] = Wv1[tid];
    (&S.Wa2[0][0])[tid]    = Wa2[tid];
    if (tid < 192) (&S.Wv2[0][0])[tid] = Wv2[tid];
    __syncthreads();

    float* a1 = out + OFF_A1 + (unsigned long long)bw * (H_ * N_ * N_);
    float* a2 = out + OFF_A2 + (unsigned long long)bw * (N_ * N_);

    // =========================== layer 1 (4 heads) ===========================
#pragma unroll 1
    for (int h = 0; h < H_; h++) {
        // stage 1: Q = QSCALE * X @ Wa1[h] ; VT = (X @ Wv1[h])^T
        {
            float q[P_], v[HID_];
#pragma unroll
            for (int j = 0; j < P_; j++) q[j] = 0.f;
#pragma unroll
            for (int o = 0; o < HID_; o++) v[o] = 0.f;
#pragma unroll
            for (int i = 0; i < P_; i++) {
                float xi = S.xT[i][tid];
#pragma unroll
                for (int j = 0; j < P_; j++) q[j] += xi * S.Wa1[h][i][j];
#pragma unroll
                for (int o = 0; o < HID_; o++) v[o] += xi * S.Wv1[h][i][o];
            }
#pragma unroll
            for (int j4 = 0; j4 < 4; j4++) {
                float4 t4 = make_float4(q[j4*4+0]*QSCALE, q[j4*4+1]*QSCALE,
                                        q[j4*4+2]*QSCALE, q[j4*4+3]*QSCALE);
                *reinterpret_cast<float4*>(&S.Qs[tid][j4*4]) = t4;
            }
#pragma unroll
            for (int o = 0; o < HID_; o++) S.VT[o][tid] = v[o];
        }
        __syncthreads();

        float* a1h = a1 + h * N_ * N_;
#pragma unroll 1
        for (int rg = 0; rg < 8; rg++) {
            const int row0 = (wid << 5) + (rg << 2);
            // packed scores s2[c][r][pair]
            u64 s2[2][4][2];
#pragma unroll
            for (int c = 0; c < 2; c++)
#pragma unroll
                for (int r = 0; r < 4; r++) { s2[c][r][0] = 0ull; s2[c][r][1] = 0ull; }
#pragma unroll
            for (int kk = 0; kk < 4; kk++) {
                float4 q4[4];
#pragma unroll
                for (int r = 0; r < 4; r++)
                    q4[r] = *reinterpret_cast<const float4*>(&S.Qs[row0 + r][kk * 4]);
#pragma unroll
                for (int k = 0; k < 4; k++) {
                    const int i = kk * 4 + k;
                    u64 qq[4];
#pragma unroll
                    for (int r = 0; r < 4; r++) {
                        float qk = (k == 0) ? q4[r].x : (k == 1) ? q4[r].y
                                 : (k == 2) ? q4[r].z : q4[r].w;
                        qq[r] = pk2(qk, qk);
                    }
#pragma unroll
                    for (int c = 0; c < 2; c++) {
                        ulonglong2 xv = *reinterpret_cast<const ulonglong2*>(
                            &S.xT[i][c * 128 + (lane << 2)]);
#pragma unroll
                        for (int r = 0; r < 4; r++) {
                            s2[c][r][0] = fma2_(qq[r], xv.x, s2[c][r][0]);
                            s2[c][r][1] = fma2_(qq[r], xv.y, s2[c][r][1]);
                        }
                    }
                }
            }
            // mask + ex2 in place; packed partial denominators
            float smr[4];
#pragma unroll
            for (int r = 0; r < 4; r++) {
                unsigned bb = S.mbL[row0 + r][lane];
                u64 dacc = 0ull;
#pragma unroll
                for (int c = 0; c < 2; c++)
#pragma unroll
                    for (int p = 0; p < 2; p++) {
                        float a_, b_; upk2(s2[c][r][p], a_, b_);
                        int kb = c * 4 + p * 2;
                        a_ = ((bb >> kb) & 1u)       ? ex2_(a_) : 0.f;
                        b_ = ((bb >> (kb + 1)) & 1u) ? ex2_(b_) : 0.f;
                        u64 e2 = pk2(a_, b_);
                        s2[c][r][p] = e2;
                        dacc = add2_(dacc, e2);
                    }
                float da, db; upk2(dacc, da, db);
                smr[r] = da + db;
            }
            // launch denominator chains (consumed AFTER aggregation)
            u64 d01 = warp_sum2(pk2(smr[0], smr[1]));
            u64 d23 = warp_sum2(pk2(smr[2], smr[3]));
            // aggregate RAW e (overlaps the SHFL chains)
            u64 acc2[4][HID_];
#pragma unroll
            for (int r = 0; r < 4; r++)
#pragma unroll
                for (int o = 0; o < HID_; o++) acc2[r][o] = 0ull;
#pragma unroll
            for (int c = 0; c < 2; c++) {
                const int m0 = c * 128 + (lane << 2);
#pragma unroll
                for (int o = 0; o < HID_; o++) {
                    ulonglong2 vv = *reinterpret_cast<const ulonglong2*>(&S.VT[o][m0]);
#pragma unroll
                    for (int r = 0; r < 4; r++) {
                        acc2[r][o] = fma2_(s2[c][r][0], vv.x, acc2[r][o]);
                        acc2[r][o] = fma2_(s2[c][r][1], vv.y, acc2[r][o]);
                    }
                }
            }
            // now consume denominators
            float inv[4];
            {
                float s0, s1, s2_, s3;
                upk2(d01, s0, s1); upk2(d23, s2_, s3);
                inv[0] = __frcp_rn(s0); inv[1] = __frcp_rn(s1);
                inv[2] = __frcp_rn(s2_); inv[3] = __frcp_rn(s3);
            }
            u64 inv2[4];
#pragma unroll
            for (int r = 0; r < 4; r++) inv2[r] = pk2(inv[r], inv[r]);
            // write normalized attn
            if (wA) {
#pragma unroll
                for (int c = 0; c < 2; c++) {
                    const int m0 = c * 128 + (lane << 2);
#pragma unroll
                    for (int r = 0; r < 4; r++) {
                        ulonglong2 st;
                        st.x = mul2_(s2[c][r][0], inv2[r]);
                        st.y = mul2_(s2[c][r][1], inv2[r]);
                        *reinterpret_cast<ulonglong2*>(&a1h[(row0 + r) * N_ + m0]) = st;
                    }
                }
            }
            // outputs: scale packed partial sums by inv, then reduce
#pragma unroll
            for (int r = 0; r < 4; r++) {
                float a0, b0, a1_, b1_, a2_, b2_, a3_, b3_;
                upk2(acc2[r][0], a0, b0);  upk2(acc2[r][1], a1_, b1_);
                upk2(acc2[r][2], a2_, b2_); upk2(acc2[r][3], a3_, b3_);
                u64 t01 = warp_sum2(mul2_(pk2(a0 + b0, a1_ + b1_), inv2[r]));
                u64 t23 = warp_sum2(mul2_(pk2(a2_ + b2_, a3_ + b3_), inv2[r]));
                if (lane == 0) {
                    float v0, v1, v2, v3;
                    upk2(t01, v0, v1); upk2(t23, v2, v3);
                    S.h1T[h * HID_ + 0][row0 + r] = v0;
                    S.h1T[h * HID_ + 1][row0 + r] = v1;
                    S.h1T[h * HID_ + 2][row0 + r] = v2;
                    S.h1T[h * HID_ + 3][row0 + r] = v3;
                }
            }
        }
        __syncthreads();
    }

    // ================================ layer 2 ================================
    {
        float q[P_], v[F_];
#pragma unroll
        for (int j = 0; j < P_; j++) q[j] = 0.f;
#pragma unroll
        for (int o = 0; o < F_; o++) v[o] = 0.f;
#pragma unroll
        for (int i = 0; i < P_; i++) {
            float xi = S.h1T[i][tid];
#pragma unroll
            for (int j = 0; j < P_; j++) q[j] += xi * S.Wa2[i][j];
#pragma unroll
            for (int o = 0; o < F_; o++) v[o] += xi * S.Wv2[i][o];
        }
#pragma unroll
        for (int j4 = 0; j4 < 4; j4++) {
            float4 t4 = make_float4(q[j4*4+0]*QSCALE, q[j4*4+1]*QSCALE,
                                    q[j4*4+2]*QSCALE, q[j4*4+3]*QSCALE);
            *reinterpret_cast<float4*>(&S.Qs[tid][j4*4]) = t4;
        }
#pragma unroll
        for (int o = 0; o < F_; o++) S.VT[o][tid] = v[o];
    }
    __syncthreads();

    // layer2: 4-row blocking, F-split aggregation (2 groups of 6 outputs)
#pragma unroll 1
    for (int rg = 0; rg < 8; rg++) {
        const int row0 = (wid << 5) + (rg << 2);
        u64 s2[2][4][2];
#pragma unroll
        for (int c = 0; c < 2; c++)
#pragma unroll
            for (int r = 0; r < 4; r++) { s2[c][r][0] = 0ull; s2[c][r][1] = 0ull; }
#pragma unroll
        for (int kk = 0; kk < 4; kk++) {
            float4 q4[4];
#pragma unroll
            for (int r = 0; r < 4; r++)
                q4[r] = *reinterpret_cast<const float4*>(&S.Qs[row0 + r][kk * 4]);
#pragma unroll
            for (int k = 0; k < 4; k++) {
                const int i = kk * 4 + k;
                u64 qq[4];
#pragma unroll
                for (int r = 0; r < 4; r++) {
                    float qk = (k == 0) ? q4[r].x : (k == 1) ? q4[r].y
                             : (k == 2) ? q4[r].z : q4[r].w;
                    qq[r] = pk2(qk, qk);
                }
#pragma unroll
                for (int c = 0; c < 2; c++) {
                    ulonglong2 xv = *reinterpret_cast<const ulonglong2*>(
                        &S.h1T[i][c * 128 + (lane << 2)]);
#pragma unroll
                    for (int r = 0; r < 4; r++) {
                        s2[c][r][0] = fma2_(qq[r], xv.x, s2[c][r][0]);
                        s2[c][r][1] = fma2_(qq[r], xv.y, s2[c][r][1]);
                    }
                }
            }
        }
        float smr[4];
#pragma unroll
        for (int r = 0; r < 4; r++) {
            unsigned bb = S.mbL[row0 + r][lane];
            u64 dacc = 0ull;
#pragma unroll
            for (int c = 0; c < 2; c++)
#pragma unroll
                for (int p = 0; p < 2; p++) {
                    float a_, b_; upk2(s2[c][r][p], a_, b_);
                    int kb = c * 4 + p * 2;
                    a_ = ((bb >> kb) & 1u)       ? ex2_(a_) : 0.f;
                    b_ = ((bb >> (kb + 1)) & 1u) ? ex2_(b_) : 0.f;
                    u64 e2 = pk2(a_, b_);
                    s2[c][r][p] = e2;
                    dacc = add2_(dacc, e2);
                }
            float da, db; upk2(dacc, da, db);
            smr[r] = da + db;
        }
        u64 d01 = warp_sum2(pk2(smr[0], smr[1]));
        u64 d23 = warp_sum2(pk2(smr[2], smr[3]));

        // ---- group 0: outputs 0..5, raw-e aggregation (overlaps chains) ----
        u64 acc2[4][6];
#pragma unroll
        for (int r = 0; r < 4; r++)
#pragma unroll
            for (int o = 0; o < 6; o++) acc2[r][o] = 0ull;
#pragma unroll
        for (int c = 0; c < 2; c++) {
            const int m0 = c * 128 + (lane << 2);
#pragma unroll
            for (int o = 0; o < 6; o++) {
                ulonglong2 vv = *reinterpret_cast<const ulonglong2*>(&S.VT[o][m0]);
#pragma unroll
                for (int r = 0; r < 4; r++) {
                    acc2[r][o] = fma2_(s2[c][r][0], vv.x, acc2[r][o]);
                    acc2[r][o] = fma2_(s2[c][r][1], vv.y, acc2[r][o]);
                }
            }
        }
        float inv[4];
        {
            float s0, s1, s2_, s3;
            upk2(d01, s0, s1); upk2(d23, s2_, s3);
            inv[0] = __frcp_rn(s0); inv[1] = __frcp_rn(s1);
            inv[2] = __frcp_rn(s2_); inv[3] = __frcp_rn(s3);
        }
        u64 inv2[4];
#pragma unroll
        for (int r = 0; r < 4; r++) inv2[r] = pk2(inv[r], inv[r]);
#pragma unroll
        for (int r = 0; r < 4; r++) {
#pragma unroll
            for (int p = 0; p < 3; p++) {
                float a0, b0, a1_, b1_;
                upk2(acc2[r][2 * p], a0, b0);
                upk2(acc2[r][2 * p + 1], a1_, b1_);
                u64 t = warp_sum2(mul2_(pk2(a0 + b0, a1_ + b1_), inv2[r]));
                if (lane == 0) {
                    float v0, v1; upk2(t, v0, v1);
                    out[((unsigned long long)bw * F_ + 2 * p) * N_ + row0 + r]     = v0;
                    out[((unsigned long long)bw * F_ + 2 * p + 1) * N_ + row0 + r] = v1;
                }
            }
        }
        // write normalized attn2
        if (wA) {
#pragma unroll
            for (int c = 0; c < 2; c++) {
                const int m0 = c * 128 + (lane << 2);
#pragma unroll
                for (int r = 0; r < 4; r++) {
                    ulonglong2 st;
                    st.x = mul2_(s2[c][r][0], inv2[r]);
                    st.y = mul2_(s2[c][r][1], inv2[r]);
                    *reinterpret_cast<ulonglong2*>(&a2[(row0 + r) * N_ + m0]) = st;
                }
            }
        }
        // ---- group 1: outputs 6..11 ----
#pragma unroll
        for (int r = 0; r < 4; r++)
#pragma unroll
            for (int o = 0; o < 6; o++) acc2[r][o] = 0ull;
#pragma unroll
        for (int c = 0; c < 2; c++) {
            const int m0 = c * 128 + (lane << 2);
#pragma unroll
            for (int o = 0; o < 6; o++) {
                ulonglong2 vv = *reinterpret_cast<const ulonglong2*>(&S.VT[6 + o][m0]);
#pragma unroll
                for (int r = 0; r < 4; r++) {
                    acc2[r][o] = fma2_(s2[c][r][0], vv.x, acc2[r][o]);
                    acc2[r][o] = fma2_(s2[c][r][1], vv.y, acc2[r][o]);
                }
            }
        }
#pragma unroll
        for (int r = 0; r < 4; r++) {
#pragma unroll
            for (int p = 0; p < 3; p++) {
                float a0, b0, a1_, b1_;
                upk2(acc2[r][2 * p], a0, b0);
                upk2(acc2[r][2 * p + 1], a1_, b1_);
                u64 t = warp_sum2(mul2_(pk2(a0 + b0, a1_ + b1_), inv2[r]));
                if (lane == 0) {
                    float v0, v1; upk2(t, v0, v1);
                    out[((unsigned long long)bw * F_ + 6 + 2 * p) * N_ + row0 + r]     = v0;
                    out[((unsigned long long)bw * F_ + 6 + 2 * p + 1) * N_ + row0 + r] = v1;
                }
            }
        }
    }
}

// ---------------------------------------------------------------------------
extern "C" void kernel_launch(void* const* d_in, const int* in_sizes, int n_in,
                              void* d_out, int out_size) {
    const float* inp  = (const float*)d_in[0];
    const int*   mask = (const int*)  d_in[1];
    const float* Wa1  = (const float*)d_in[2];
    const float* Wv1  = (const float*)d_in[3];
    const float* Wa2  = (const float*)d_in[4];
    const float* Wv2  = (const float*)d_in[5];
    float* out = (float*)d_out;

    const int wA = (out_size >= (int)(OFF_A2 + (unsigned long long)BW_ * N_ * N_)) ? 1 : 0;
    const int wW = (out_size >= (int)TOT_FULL) ? 1 : 0;

    cudaFuncSetAttribute(spatial_attn_kernel,
                         cudaFuncAttributeMaxDynamicSharedMemorySize,
                         (int)sizeof(Smem));

    pack_mask_kernel<<<N_, 256>>>(mask, Wv1, Wv2, out, wW);
    spatial_attn_kernel<<<BW_, 256, sizeof(Smem)>>>(inp, Wa1, Wv1, Wa2, Wv2, out, wA);
}